// round 4
// baseline (speedup 1.0000x reference)
#include <cuda_runtime.h>
#include <cuda_bf16.h>
#include <math.h>
#include <stdint.h>

// TopKRouter: logits = x @ W^T (16384x4096 @ 4096x64), softmax, top-2, renorm.
// Split-bf16 (hi/lo) 3-product mma.sync.m16n8k16 GEMM, zero smem, zero CTA sync.
// Round 4: 512 CTAs x 64 thr (2x warp concurrency) + 2-deep A prefetch.
// out fp32: [indices 16384*2][weights 16384*2][logits 16384*64]

#define TOKENS 16384
#define DIM    4096
#define NEXP   64
#define NKS    (DIM / 16)   // 256 k-steps

// Fragment-ordered pre-converted W: index q = ((ks*8 + nt)*32 + lane), uint2:
//   .x = bf16x2( W[n][kb], W[n][kb+1] ),  .y = bf16x2( W[n][kb+8], W[n][kb+9] )
// with n = nt*8 + lane/4, kb = ks*16 + (lane%4)*2.
__device__ uint2 g_Bh[NKS * 8 * 32];
__device__ uint2 g_Bl[NKS * 8 * 32];

// split two fp32 into bf16x2 hi (round-nearest) and bf16x2 lo (residual).
__device__ __forceinline__ void split2(float a, float b, unsigned& h, unsigned& l) {
    asm("cvt.rn.bf16x2.f32 %0, %1, %2;" : "=r"(h) : "f"(b), "f"(a));
    float ha = __uint_as_float(h << 16);
    float hb = __uint_as_float(h & 0xFFFF0000u);
    float ra = a - ha;
    float rb = b - hb;
    asm("cvt.rn.bf16x2.f32 %0, %1, %2;" : "=r"(l) : "f"(rb), "f"(ra));
}

__device__ __forceinline__ void mma16816(float* c, unsigned a0, unsigned a1,
                                         unsigned a2, unsigned a3, uint2 b) {
    asm volatile(
        "mma.sync.aligned.m16n8k16.row.col.f32.bf16.bf16.f32 "
        "{%0,%1,%2,%3}, {%4,%5,%6,%7}, {%8,%9}, {%0,%1,%2,%3};"
        : "+f"(c[0]), "+f"(c[1]), "+f"(c[2]), "+f"(c[3])
        : "r"(a0), "r"(a1), "r"(a2), "r"(a3), "r"(b.x), "r"(b.y));
}

// ---------------- W pre-convert (fragment order) ----------------
__global__ void convert_w_kernel(const float* __restrict__ Wg) {
    int q = blockIdx.x * blockDim.x + threadIdx.x;   // 0..65535
    int ks   = q >> 8;
    int nt   = (q >> 5) & 7;
    int lane = q & 31;
    int n  = nt * 8 + (lane >> 2);
    int kb = ks * 16 + (lane & 3) * 2;
    const float* wr = Wg + (size_t)n * DIM + kb;
    unsigned hx, lx, hy, ly;
    split2(wr[0], wr[1], hx, lx);
    split2(wr[8], wr[9], hy, ly);
    g_Bh[q] = make_uint2(hx, hy);
    g_Bl[q] = make_uint2(lx, ly);
}

__device__ __forceinline__ bool better(float v, int i, float v2, int i2) {
    return (v > v2) || (v == v2 && i < i2);
}

// ---------------- main kernel ----------------
__global__ __launch_bounds__(64) void router_kernel(
    const float* __restrict__ x,
    float* __restrict__ out)
{
    const int tid  = threadIdx.x;
    const int wid  = tid >> 5;
    const int lane = tid & 31;
    const int tok0 = blockIdx.x * 32 + wid * 16;   // warp's 16-token tile
    const int r0   = tok0 + (lane >> 2);           // this thread's rows: r0, r0+8

    // A pointers: float2 granularity; element k0 = (lane%4)*2 within each k-step
    const float2* pA0 = (const float2*)(x + (size_t)r0 * DIM) + (lane & 3);
    const float2* pA1 = pA0 + 4 * DIM;             // row r0+8 : +8*DIM floats

    float acc[8][4];
    #pragma unroll
    for (int nt = 0; nt < 8; nt++)
        #pragma unroll
        for (int j = 0; j < 4; j++) acc[nt][j] = 0.0f;

    const uint2* __restrict__ Bh = g_Bh + lane;
    const uint2* __restrict__ Bl = g_Bl + lane;

    // 2-deep A prefetch: loads for step ks+1 are in flight during step ks's MMAs
    float2 n00 = __ldg(pA0);
    float2 n01 = __ldg(pA0 + 4);
    float2 n10 = __ldg(pA1);
    float2 n11 = __ldg(pA1 + 4);

    #pragma unroll 2
    for (int ks = 0; ks < NKS; ks++) {
        float2 v00 = n00, v01 = n01, v10 = n10, v11 = n11;
        if (ks + 1 < NKS) {
            n00 = __ldg(pA0 + (ks + 1) * 8);
            n01 = __ldg(pA0 + (ks + 1) * 8 + 4);
            n10 = __ldg(pA1 + (ks + 1) * 8);
            n11 = __ldg(pA1 + (ks + 1) * 8 + 4);
        }

        unsigned ah0, ah1, ah2, ah3, al0, al1, al2, al3;
        split2(v00.x, v00.y, ah0, al0);
        split2(v10.x, v10.y, ah1, al1);
        split2(v01.x, v01.y, ah2, al2);
        split2(v11.x, v11.y, ah3, al3);

        const uint2* bh = Bh + ks * 256;
        const uint2* bl = Bl + ks * 256;
        #pragma unroll
        for (int nt = 0; nt < 8; nt++) {
            uint2 bhv = __ldg(bh + nt * 32);
            uint2 blv = __ldg(bl + nt * 32);
            mma16816(acc[nt], ah0, ah1, ah2, ah3, bhv);   // hi * hi
            mma16816(acc[nt], ah0, ah1, ah2, ah3, blv);   // hi * lo
            mma16816(acc[nt], al0, al1, al2, al3, bhv);   // lo * hi
        }
    }

    // ---- write logits straight from accumulators ----
    float* lg = out + 4 * TOKENS;
    const int cbase = (lane & 3) * 2;
    #pragma unroll
    for (int nt = 0; nt < 8; nt++) {
        int c = nt * 8 + cbase;
        *(float2*)(lg + (size_t)r0 * NEXP + c)       = make_float2(acc[nt][0], acc[nt][1]);
        *(float2*)(lg + (size_t)(r0 + 8) * NEXP + c) = make_float2(acc[nt][2], acc[nt][3]);
    }

    // ---- per-row top-2 (register scan + quad shuffle merge) ----
    #pragma unroll
    for (int half = 0; half < 2; half++) {
        const int row = r0 + half * 8;
        float m1 = -INFINITY, m2 = -INFINITY;
        int i1 = 0, i2 = 0;
        #pragma unroll
        for (int nt = 0; nt < 8; nt++) {
            #pragma unroll
            for (int j = 0; j < 2; j++) {
                float v = acc[nt][half * 2 + j];
                int e = nt * 8 + cbase + j;
                if (v > m1)      { m2 = m1; i2 = i1; m1 = v; i1 = e; }
                else if (v > m2) { m2 = v; i2 = e; }
            }
        }
        #pragma unroll
        for (int d = 1; d < 4; d <<= 1) {
            float om1 = __shfl_xor_sync(0xFFFFFFFF, m1, d);
            int   oi1 = __shfl_xor_sync(0xFFFFFFFF, i1, d);
            float om2 = __shfl_xor_sync(0xFFFFFFFF, m2, d);
            int   oi2 = __shfl_xor_sync(0xFFFFFFFF, i2, d);
            if (better(om1, oi1, m1, i1)) {
                float nm2; int ni2;
                if (better(m1, i1, om2, oi2)) { nm2 = m1; ni2 = i1; }
                else                          { nm2 = om2; ni2 = oi2; }
                m1 = om1; i1 = oi1; m2 = nm2; i2 = ni2;
            } else {
                if (better(om1, oi1, m2, i2)) { m2 = om1; i2 = oi1; }
            }
        }
        if ((lane & 3) == 0) {
            // top-2 renorm of full softmax == logistic of (m1 - m2); +1e-9 negligible
            float e2 = __expf(m2 - m1);
            float rcp = 1.0f / (1.0f + e2);
            out[(size_t)row * 2 + 0] = (float)i1;
            out[(size_t)row * 2 + 1] = (float)i2;
            out[2 * TOKENS + (size_t)row * 2 + 0] = rcp;
            out[2 * TOKENS + (size_t)row * 2 + 1] = e2 * rcp;
        }
    }
}

extern "C" void kernel_launch(void* const* d_in, const int* in_sizes, int n_in,
                              void* d_out, int out_size)
{
    const float* x  = (const float*)d_in[0];
    const float* Wg = (const float*)d_in[1];
    float* out = (float*)d_out;

    convert_w_kernel<<<256, 256>>>(Wg);
    router_kernel<<<TOKENS / 32, 64>>>(x, out);
}

// round 5
// speedup vs baseline: 3.4642x; 3.4642x over previous
#include <cuda_runtime.h>
#include <cuda_bf16.h>
#include <math.h>
#include <stdint.h>

// TopKRouter: logits = x @ W^T (16384x4096 @ 4096x64), softmax, top-2, renorm.
// Split-bf16 (hi/lo) 3-product mma.sync.m16n8k16 GEMM.
// Round 5: K-split x4 across the CTA's warps (4096 warps total) + smem reduce.
// out fp32: [indices 16384*2][weights 16384*2][logits 16384*64]

#define TOKENS 16384
#define DIM    4096
#define NEXP   64
#define NKS    (DIM / 16)   // 256 k-steps total
#define KSW    (NKS / 4)    // 64 k-steps per warp

// Fragment-ordered pre-converted W: index q = ((ks*8 + nt)*32 + lane), uint2:
//   .x = bf16x2( W[n][kb], W[n][kb+1] ),  .y = bf16x2( W[n][kb+8], W[n][kb+9] )
// with n = nt*8 + lane/4, kb = ks*16 + (lane%4)*2.
__device__ uint2 g_Bh[NKS * 8 * 32];
__device__ uint2 g_Bl[NKS * 8 * 32];

__device__ __forceinline__ void split2(float a, float b, unsigned& h, unsigned& l) {
    asm("cvt.rn.bf16x2.f32 %0, %1, %2;" : "=r"(h) : "f"(b), "f"(a));
    float ha = __uint_as_float(h << 16);
    float hb = __uint_as_float(h & 0xFFFF0000u);
    float ra = a - ha;
    float rb = b - hb;
    asm("cvt.rn.bf16x2.f32 %0, %1, %2;" : "=r"(l) : "f"(rb), "f"(ra));
}

__device__ __forceinline__ void mma16816(float* c, unsigned a0, unsigned a1,
                                         unsigned a2, unsigned a3, uint2 b) {
    asm volatile(
        "mma.sync.aligned.m16n8k16.row.col.f32.bf16.bf16.f32 "
        "{%0,%1,%2,%3}, {%4,%5,%6,%7}, {%8,%9}, {%0,%1,%2,%3};"
        : "+f"(c[0]), "+f"(c[1]), "+f"(c[2]), "+f"(c[3])
        : "r"(a0), "r"(a1), "r"(a2), "r"(a3), "r"(b.x), "r"(b.y));
}

// ---------------- W pre-convert (fragment order) ----------------
__global__ void convert_w_kernel(const float* __restrict__ Wg) {
    int q = blockIdx.x * blockDim.x + threadIdx.x;   // 0..65535
    int ks   = q >> 8;
    int nt   = (q >> 5) & 7;
    int lane = q & 31;
    int n  = nt * 8 + (lane >> 2);
    int kb = ks * 16 + (lane & 3) * 2;
    const float* wr = Wg + (size_t)n * DIM + kb;
    unsigned hx, lx, hy, ly;
    split2(wr[0], wr[1], hx, lx);
    split2(wr[8], wr[9], hy, ly);
    g_Bh[q] = make_uint2(hx, hy);
    g_Bl[q] = make_uint2(lx, ly);
}

__device__ __forceinline__ bool better(float v, int i, float v2, int i2) {
    return (v > v2) || (v == v2 && i < i2);
}

// ---------------- main kernel ----------------
// CTA: 4 warps, same 16 tokens, K quarters. Partial-acc reduce through smem.
__global__ __launch_bounds__(128, 2) void router_kernel(
    const float* __restrict__ x,
    float* __restrict__ out)
{
    __shared__ float red[3 * 32 * 33];   // 3 partials x 32 lanes x 32 floats, pad 33

    const int tid  = threadIdx.x;
    const int wid  = tid >> 5;           // K quarter 0..3
    const int lane = tid & 31;
    const int r0   = blockIdx.x * 16 + (lane >> 2);   // rows r0, r0+8
    const int kbase = wid * KSW;

    const float2* pA0 = (const float2*)(x + (size_t)r0 * DIM) + (lane & 3);
    const float2* pA1 = pA0 + 4 * DIM;   // row r0+8

    float acc[8][4];
    #pragma unroll
    for (int nt = 0; nt < 8; nt++)
        #pragma unroll
        for (int j = 0; j < 4; j++) acc[nt][j] = 0.0f;

    const uint2* __restrict__ Bh = g_Bh + lane;
    const uint2* __restrict__ Bl = g_Bl + lane;

    #pragma unroll 2
    for (int s = 0; s < KSW; s++) {
        const int ks = kbase + s;
        float2 v00 = __ldg(pA0 + ks * 8);
        float2 v01 = __ldg(pA0 + ks * 8 + 4);
        float2 v10 = __ldg(pA1 + ks * 8);
        float2 v11 = __ldg(pA1 + ks * 8 + 4);

        unsigned ah0, ah1, ah2, ah3, al0, al1, al2, al3;
        split2(v00.x, v00.y, ah0, al0);
        split2(v10.x, v10.y, ah1, al1);
        split2(v01.x, v01.y, ah2, al2);
        split2(v11.x, v11.y, ah3, al3);

        const uint2* bh = Bh + ks * 256;
        const uint2* bl = Bl + ks * 256;
        #pragma unroll
        for (int nt = 0; nt < 8; nt++) {
            uint2 bhv = __ldg(bh + nt * 32);
            uint2 blv = __ldg(bl + nt * 32);
            mma16816(acc[nt], ah0, ah1, ah2, ah3, bhv);   // hi * hi
            mma16816(acc[nt], ah0, ah1, ah2, ah3, blv);   // hi * lo
            mma16816(acc[nt], al0, al1, al2, al3, bhv);   // lo * hi
        }
    }

    // ---- cross-warp K reduction via smem ----
    if (wid != 0) {
        float* dst = red + ((wid - 1) * 32 + lane) * 33;
        #pragma unroll
        for (int nt = 0; nt < 8; nt++)
            #pragma unroll
            for (int j = 0; j < 4; j++)
                dst[nt * 4 + j] = acc[nt][j];
    }
    __syncthreads();
    if (wid != 0) return;

    #pragma unroll
    for (int p = 0; p < 3; p++) {
        const float* src = red + (p * 32 + lane) * 33;
        #pragma unroll
        for (int nt = 0; nt < 8; nt++)
            #pragma unroll
            for (int j = 0; j < 4; j++)
                acc[nt][j] += src[nt * 4 + j];
    }

    // ---- write logits ----
    float* lg = out + 4 * TOKENS;
    const int cbase = (lane & 3) * 2;
    #pragma unroll
    for (int nt = 0; nt < 8; nt++) {
        int c = nt * 8 + cbase;
        *(float2*)(lg + (size_t)r0 * NEXP + c)       = make_float2(acc[nt][0], acc[nt][1]);
        *(float2*)(lg + (size_t)(r0 + 8) * NEXP + c) = make_float2(acc[nt][2], acc[nt][3]);
    }

    // ---- per-row top-2 (register scan + quad shuffle merge) ----
    #pragma unroll
    for (int half = 0; half < 2; half++) {
        const int row = r0 + half * 8;
        float m1 = -INFINITY, m2 = -INFINITY;
        int i1 = 0, i2 = 0;
        #pragma unroll
        for (int nt = 0; nt < 8; nt++) {
            #pragma unroll
            for (int j = 0; j < 2; j++) {
                float v = acc[nt][half * 2 + j];
                int e = nt * 8 + cbase + j;
                if (v > m1)      { m2 = m1; i2 = i1; m1 = v; i1 = e; }
                else if (v > m2) { m2 = v; i2 = e; }
            }
        }
        #pragma unroll
        for (int d = 1; d < 4; d <<= 1) {
            float om1 = __shfl_xor_sync(0xFFFFFFFF, m1, d);
            int   oi1 = __shfl_xor_sync(0xFFFFFFFF, i1, d);
            float om2 = __shfl_xor_sync(0xFFFFFFFF, m2, d);
            int   oi2 = __shfl_xor_sync(0xFFFFFFFF, i2, d);
            if (better(om1, oi1, m1, i1)) {
                float nm2; int ni2;
                if (better(m1, i1, om2, oi2)) { nm2 = m1; ni2 = i1; }
                else                          { nm2 = om2; ni2 = oi2; }
                m1 = om1; i1 = oi1; m2 = nm2; i2 = ni2;
            } else {
                if (better(om1, oi1, m2, i2)) { m2 = om1; i2 = oi1; }
            }
        }
        if ((lane & 3) == 0) {
            // top-2 renorm of full softmax == logistic of (m1 - m2); +1e-9 negligible
            float e2 = __expf(m2 - m1);
            float rcp = 1.0f / (1.0f + e2);
            out[(size_t)row * 2 + 0] = (float)i1;
            out[(size_t)row * 2 + 1] = (float)i2;
            out[2 * TOKENS + (size_t)row * 2 + 0] = rcp;
            out[2 * TOKENS + (size_t)row * 2 + 1] = e2 * rcp;
        }
    }
}

extern "C" void kernel_launch(void* const* d_in, const int* in_sizes, int n_in,
                              void* d_out, int out_size)
{
    const float* x  = (const float*)d_in[0];
    const float* Wg = (const float*)d_in[1];
    float* out = (float*)d_out;

    convert_w_kernel<<<256, 256>>>(Wg);
    router_kernel<<<TOKENS / 16, 128>>>(x, out);
}

// round 6
// speedup vs baseline: 4.5755x; 1.3208x over previous
#include <cuda_runtime.h>
#include <cuda_bf16.h>
#include <math.h>
#include <stdint.h>

// TopKRouter: logits = x @ W^T (16384x4096 @ 4096x64), softmax, top-2, renorm.
// Split-bf16 (hi/lo) 3-product mma.sync.m16n8k16 GEMM, K-split x4 across warps.
// Round 6: cap regs at 128 (4 CTAs/SM) + pack B hi/lo into uint4 (LDG.128).
// out fp32: [indices 16384*2][weights 16384*2][logits 16384*64]

#define TOKENS 16384
#define DIM    4096
#define NEXP   64
#define NKS    (DIM / 16)   // 256 k-steps total
#define KSW    (NKS / 4)    // 64 k-steps per warp

// Fragment-ordered pre-converted W, hi and lo interleaved:
// q = ((ks*8 + nt)*32 + lane): uint4 { hi(kb,kb+1), hi(kb+8,kb+9),
//                                      lo(kb,kb+1), lo(kb+8,kb+9) }
// with n = nt*8 + lane/4, kb = ks*16 + (lane%4)*2.
__device__ uint4 g_B[NKS * 8 * 32];

__device__ __forceinline__ void split2(float a, float b, unsigned& h, unsigned& l) {
    asm("cvt.rn.bf16x2.f32 %0, %1, %2;" : "=r"(h) : "f"(b), "f"(a));
    float ha = __uint_as_float(h << 16);
    float hb = __uint_as_float(h & 0xFFFF0000u);
    float ra = a - ha;
    float rb = b - hb;
    asm("cvt.rn.bf16x2.f32 %0, %1, %2;" : "=r"(l) : "f"(rb), "f"(ra));
}

__device__ __forceinline__ void mma16816(float* c, unsigned a0, unsigned a1,
                                         unsigned a2, unsigned a3,
                                         unsigned b0, unsigned b1) {
    asm volatile(
        "mma.sync.aligned.m16n8k16.row.col.f32.bf16.bf16.f32 "
        "{%0,%1,%2,%3}, {%4,%5,%6,%7}, {%8,%9}, {%0,%1,%2,%3};"
        : "+f"(c[0]), "+f"(c[1]), "+f"(c[2]), "+f"(c[3])
        : "r"(a0), "r"(a1), "r"(a2), "r"(a3), "r"(b0), "r"(b1));
}

// ---------------- W pre-convert (fragment order, interleaved) ----------------
__global__ void convert_w_kernel(const float* __restrict__ Wg) {
    int q = blockIdx.x * blockDim.x + threadIdx.x;   // 0..65535
    int ks   = q >> 8;
    int nt   = (q >> 5) & 7;
    int lane = q & 31;
    int n  = nt * 8 + (lane >> 2);
    int kb = ks * 16 + (lane & 3) * 2;
    const float* wr = Wg + (size_t)n * DIM + kb;
    unsigned hx, lx, hy, ly;
    split2(wr[0], wr[1], hx, lx);
    split2(wr[8], wr[9], hy, ly);
    g_B[q] = make_uint4(hx, hy, lx, ly);
}

__device__ __forceinline__ bool better(float v, int i, float v2, int i2) {
    return (v > v2) || (v == v2 && i < i2);
}

// ---------------- main kernel ----------------
// CTA: 4 warps, same 16 tokens, K quarters. Partial-acc reduce through smem.
__global__ __launch_bounds__(128, 4) void router_kernel(
    const float* __restrict__ x,
    float* __restrict__ out)
{
    __shared__ float red[3 * 32 * 33];   // 3 partials x 32 lanes x 32 floats, pad 33

    const int tid  = threadIdx.x;
    const int wid  = tid >> 5;           // K quarter 0..3
    const int lane = tid & 31;
    const int r0   = blockIdx.x * 16 + (lane >> 2);   // rows r0, r0+8
    const int kbase = wid * KSW;

    const float2* pA0 = (const float2*)(x + (size_t)r0 * DIM) + (lane & 3);
    const float2* pA1 = pA0 + 4 * DIM;   // row r0+8

    float acc[8][4];
    #pragma unroll
    for (int nt = 0; nt < 8; nt++)
        #pragma unroll
        for (int j = 0; j < 4; j++) acc[nt][j] = 0.0f;

    const uint4* __restrict__ B = g_B + lane;

    #pragma unroll 2
    for (int s = 0; s < KSW; s++) {
        const int ks = kbase + s;
        float2 v00 = __ldg(pA0 + ks * 8);
        float2 v01 = __ldg(pA0 + ks * 8 + 4);
        float2 v10 = __ldg(pA1 + ks * 8);
        float2 v11 = __ldg(pA1 + ks * 8 + 4);

        unsigned ah0, ah1, ah2, ah3, al0, al1, al2, al3;
        split2(v00.x, v00.y, ah0, al0);
        split2(v10.x, v10.y, ah1, al1);
        split2(v01.x, v01.y, ah2, al2);
        split2(v11.x, v11.y, ah3, al3);

        const uint4* b = B + ks * 256;
        #pragma unroll
        for (int nt = 0; nt < 8; nt++) {
            uint4 bv = __ldg(b + nt * 32);
            mma16816(acc[nt], ah0, ah1, ah2, ah3, bv.x, bv.y);   // hi * hi
            mma16816(acc[nt], ah0, ah1, ah2, ah3, bv.z, bv.w);   // hi * lo
            mma16816(acc[nt], al0, al1, al2, al3, bv.x, bv.y);   // lo * hi
        }
    }

    // ---- cross-warp K reduction via smem ----
    if (wid != 0) {
        float* dst = red + ((wid - 1) * 32 + lane) * 33;
        #pragma unroll
        for (int nt = 0; nt < 8; nt++)
            #pragma unroll
            for (int j = 0; j < 4; j++)
                dst[nt * 4 + j] = acc[nt][j];
    }
    __syncthreads();
    if (wid != 0) return;

    #pragma unroll
    for (int p = 0; p < 3; p++) {
        const float* src = red + (p * 32 + lane) * 33;
        #pragma unroll
        for (int nt = 0; nt < 8; nt++)
            #pragma unroll
            for (int j = 0; j < 4; j++)
                acc[nt][j] += src[nt * 4 + j];
    }

    // ---- write logits ----
    float* lg = out + 4 * TOKENS;
    const int cbase = (lane & 3) * 2;
    #pragma unroll
    for (int nt = 0; nt < 8; nt++) {
        int c = nt * 8 + cbase;
        *(float2*)(lg + (size_t)r0 * NEXP + c)       = make_float2(acc[nt][0], acc[nt][1]);
        *(float2*)(lg + (size_t)(r0 + 8) * NEXP + c) = make_float2(acc[nt][2], acc[nt][3]);
    }

    // ---- per-row top-2 (register scan + quad shuffle merge) ----
    #pragma unroll
    for (int half = 0; half < 2; half++) {
        const int row = r0 + half * 8;
        float m1 = -INFINITY, m2 = -INFINITY;
        int i1 = 0, i2 = 0;
        #pragma unroll
        for (int nt = 0; nt < 8; nt++) {
            #pragma unroll
            for (int j = 0; j < 2; j++) {
                float v = acc[nt][half * 2 + j];
                int e = nt * 8 + cbase + j;
                if (v > m1)      { m2 = m1; i2 = i1; m1 = v; i1 = e; }
                else if (v > m2) { m2 = v; i2 = e; }
            }
        }
        #pragma unroll
        for (int d = 1; d < 4; d <<= 1) {
            float om1 = __shfl_xor_sync(0xFFFFFFFF, m1, d);
            int   oi1 = __shfl_xor_sync(0xFFFFFFFF, i1, d);
            float om2 = __shfl_xor_sync(0xFFFFFFFF, m2, d);
            int   oi2 = __shfl_xor_sync(0xFFFFFFFF, i2, d);
            if (better(om1, oi1, m1, i1)) {
                float nm2; int ni2;
                if (better(m1, i1, om2, oi2)) { nm2 = m1; ni2 = i1; }
                else                          { nm2 = om2; ni2 = oi2; }
                m1 = om1; i1 = oi1; m2 = nm2; i2 = ni2;
            } else {
                if (better(om1, oi1, m2, i2)) { m2 = om1; i2 = oi1; }
            }
        }
        if ((lane & 3) == 0) {
            // top-2 renorm of full softmax == logistic of (m1 - m2); +1e-9 negligible
            float e2 = __expf(m2 - m1);
            float rcp = 1.0f / (1.0f + e2);
            out[(size_t)row * 2 + 0] = (float)i1;
            out[(size_t)row * 2 + 1] = (float)i2;
            out[2 * TOKENS + (size_t)row * 2 + 0] = rcp;
            out[2 * TOKENS + (size_t)row * 2 + 1] = e2 * rcp;
        }
    }
}

extern "C" void kernel_launch(void* const* d_in, const int* in_sizes, int n_in,
                              void* d_out, int out_size)
{
    const float* x  = (const float*)d_in[0];
    const float* Wg = (const float*)d_in[1];
    float* out = (float*)d_out;

    convert_w_kernel<<<256, 256>>>(Wg);
    router_kernel<<<TOKENS / 16, 128>>>(x, out);
}